// round 2
// baseline (speedup 1.0000x reference)
#include <cuda_runtime.h>

#define HIDDEN 1024
#define HEADS  16
#define HEADD  64
#define BATCH  2
#define SEQ    2048
#define M_TOT  (BATCH * SEQ)   // 4096 rows

// ---------------------------------------------------------------------------
// Scratch (no cudaMalloc allowed): 5 x 16MB fp32 buffers
// ---------------------------------------------------------------------------
__device__ float g_xn [M_TOT * HIDDEN];
__device__ float g_q  [M_TOT * HIDDEN];
__device__ float g_k  [M_TOT * HIDDEN];
__device__ float g_v  [M_TOT * HIDDEN];
__device__ float g_ctx[M_TOT * HIDDEN];

// ---------------------------------------------------------------------------
// LayerNorm: one block per row, 256 threads, float4 loads
// ---------------------------------------------------------------------------
__global__ __launch_bounds__(256) void ln_kernel(
    const float* __restrict__ x, const float* __restrict__ gam,
    const float* __restrict__ bet, float* __restrict__ out)
{
    int row = blockIdx.x;
    int tid = threadIdx.x;                       // 256 threads, 4 floats each
    const float4* xr = (const float4*)(x + (size_t)row * HIDDEN);
    float4 v = xr[tid];
    float s  = v.x + v.y + v.z + v.w;
    float ss = v.x * v.x + v.y * v.y + v.z * v.z + v.w * v.w;
    #pragma unroll
    for (int o = 16; o > 0; o >>= 1) {
        s  += __shfl_xor_sync(0xFFFFFFFFu, s,  o);
        ss += __shfl_xor_sync(0xFFFFFFFFu, ss, o);
    }
    __shared__ float sh_s[8], sh_ss[8];
    int w = tid >> 5, lane = tid & 31;
    if (lane == 0) { sh_s[w] = s; sh_ss[w] = ss; }
    __syncthreads();
    s = 0.f; ss = 0.f;
    #pragma unroll
    for (int i = 0; i < 8; i++) { s += sh_s[i]; ss += sh_ss[i]; }
    float mean = s * (1.f / HIDDEN);
    float var  = ss * (1.f / HIDDEN) - mean * mean;
    float rstd = rsqrtf(var + 1e-5f);
    float4 g = ((const float4*)gam)[tid];
    float4 b = ((const float4*)bet)[tid];
    float4 o;
    o.x = (v.x - mean) * rstd * g.x + b.x;
    o.y = (v.y - mean) * rstd * g.y + b.y;
    o.z = (v.z - mean) * rstd * g.z + b.z;
    o.w = (v.w - mean) * rstd * g.w + b.w;
    ((float4*)(out + (size_t)row * HIDDEN))[tid] = o;
}

// ---------------------------------------------------------------------------
// SGEMM: C[M,N] = A[M,K] * W[N,K]^T + bias (+ residual)
// 128x128 tile, BK=8, 256 threads, 8x8 register micro-tile, prefetch 1 deep
// ---------------------------------------------------------------------------
#define GBM 128
#define GBN 128
#define GBK 8

__global__ __launch_bounds__(256) void gemm_kernel(
    const float* __restrict__ A, const float* __restrict__ W,
    const float* __restrict__ bias, const float* __restrict__ resid,
    float* __restrict__ C, int M, int N, int K)
{
    __shared__ float As[GBK][GBM + 4];  // +4 pad: kills store bank conflicts,
    __shared__ float Bs[GBK][GBM + 4];  // keeps 16B alignment (132*4=528=33*16)
    int tid = threadIdx.x;
    int bn = blockIdx.x, bm = blockIdx.y;
    int tx = tid & 15, ty = tid >> 4;
    int lrow = tid >> 1;                 // 0..127
    int lk   = (tid & 1) << 2;           // 0 or 4

    const float* Ap = A + (size_t)(bm * GBM + lrow) * K + lk;
    const float* Wp = W + (size_t)(bn * GBN + lrow) * K + lk;

    float acc[8][8];
    #pragma unroll
    for (int i = 0; i < 8; i++)
        #pragma unroll
        for (int j = 0; j < 8; j++) acc[i][j] = 0.f;

    float4 av = *(const float4*)Ap;
    float4 wv = *(const float4*)Wp;

    for (int k0 = 0; k0 < K; k0 += GBK) {
        __syncthreads();
        As[lk + 0][lrow] = av.x; As[lk + 1][lrow] = av.y;
        As[lk + 2][lrow] = av.z; As[lk + 3][lrow] = av.w;
        Bs[lk + 0][lrow] = wv.x; Bs[lk + 1][lrow] = wv.y;
        Bs[lk + 2][lrow] = wv.z; Bs[lk + 3][lrow] = wv.w;
        __syncthreads();
        if (k0 + GBK < K) {                       // prefetch next tile
            av = *(const float4*)(Ap + k0 + GBK);
            wv = *(const float4*)(Wp + k0 + GBK);
        }
        #pragma unroll
        for (int kk = 0; kk < GBK; kk++) {
            float a[8], b[8];
            *(float4*)&a[0] = *(const float4*)&As[kk][ty * 8];
            *(float4*)&a[4] = *(const float4*)&As[kk][ty * 8 + 4];
            *(float4*)&b[0] = *(const float4*)&Bs[kk][tx * 8];
            *(float4*)&b[4] = *(const float4*)&Bs[kk][tx * 8 + 4];
            #pragma unroll
            for (int i = 0; i < 8; i++)
                #pragma unroll
                for (int j = 0; j < 8; j++)
                    acc[i][j] = fmaf(a[i], b[j], acc[i][j]);
        }
    }

    int col = bn * GBN + tx * 8;
    float bsum[8];
    {
        const float4* bp = (const float4*)(bias + col);
        float4 b0 = bp[0], b1 = bp[1];
        bsum[0] = b0.x; bsum[1] = b0.y; bsum[2] = b0.z; bsum[3] = b0.w;
        bsum[4] = b1.x; bsum[5] = b1.y; bsum[6] = b1.z; bsum[7] = b1.w;
    }
    #pragma unroll
    for (int i = 0; i < 8; i++) {
        int row = bm * GBM + ty * 8 + i;
        float out[8];
        #pragma unroll
        for (int j = 0; j < 8; j++) out[j] = acc[i][j] + bsum[j];
        if (resid) {
            const float4* rp = (const float4*)(resid + (size_t)row * N + col);
            float4 r0 = rp[0], r1 = rp[1];
            out[0] += r0.x; out[1] += r0.y; out[2] += r0.z; out[3] += r0.w;
            out[4] += r1.x; out[5] += r1.y; out[6] += r1.z; out[7] += r1.w;
        }
        float4* cp = (float4*)(C + (size_t)row * N + col);
        cp[0] = *(float4*)&out[0];
        cp[1] = *(float4*)&out[4];
    }
}

// ---------------------------------------------------------------------------
// Flash attention (fp32): 1 thread = 1 query row (q,o in registers),
// K/V staged in smem in 64-row tiles, online softmax in chunks of 16.
// grid: (SEQ/128, HEADS, BATCH), block: 128
// ---------------------------------------------------------------------------
__global__ __launch_bounds__(128) void attn_kernel(
    const float* __restrict__ Q, const float* __restrict__ Kp,
    const float* __restrict__ V, float* __restrict__ O)
{
    __shared__ float Ks[64][64];
    __shared__ float Vs[64][64];
    int tid  = threadIdx.x;
    int h = blockIdx.y, b = blockIdx.z;
    int qrow = blockIdx.x * 128 + tid;
    size_t headoff = (size_t)b * SEQ * HIDDEN + (size_t)h * HEADD;

    const float4* qp = (const float4*)(Q + headoff + (size_t)qrow * HIDDEN);
    float4 q[16];
    #pragma unroll
    for (int i = 0; i < 16; i++) {
        float4 t = qp[i];                        // fold 1/sqrt(64) into q
        q[i] = make_float4(t.x * 0.125f, t.y * 0.125f, t.z * 0.125f, t.w * 0.125f);
    }
    float4 o[16];
    #pragma unroll
    for (int i = 0; i < 16; i++) o[i] = make_float4(0.f, 0.f, 0.f, 0.f);
    float m = -1e30f, l = 0.f;

    for (int kt = 0; kt < SEQ; kt += 64) {
        const float4* kp = (const float4*)(Kp + headoff + (size_t)kt * HIDDEN);
        const float4* vp = (const float4*)(V  + headoff + (size_t)kt * HIDDEN);
        __syncthreads();                         // previous tile fully consumed
        #pragma unroll
        for (int i = 0; i < 8; i++) {
            int idx = tid + i * 128;             // 1024 float4 per tile
            int r = idx >> 4, c = idx & 15;
            ((float4*)Ks)[idx] = kp[(size_t)r * (HIDDEN / 4) + c];
            ((float4*)Vs)[idx] = vp[(size_t)r * (HIDDEN / 4) + c];
        }
        __syncthreads();

        for (int jc = 0; jc < 64; jc += 16) {    // 16-score chunks
            float sv[16];
            #pragma unroll
            for (int j = 0; j < 16; j++) {
                const float4* kr = (const float4*)&Ks[jc + j][0];
                float s0 = 0.f, s1 = 0.f, s2 = 0.f, s3 = 0.f;
                #pragma unroll
                for (int d = 0; d < 16; d += 4) {  // 4 independent accumulators
                    float4 k0 = kr[d], k1 = kr[d + 1], k2 = kr[d + 2], k3 = kr[d + 3];
                    s0 = fmaf(q[d].w,   k0.w, fmaf(q[d].z,   k0.z, fmaf(q[d].y,   k0.y, fmaf(q[d].x,   k0.x, s0))));
                    s1 = fmaf(q[d+1].w, k1.w, fmaf(q[d+1].z, k1.z, fmaf(q[d+1].y, k1.y, fmaf(q[d+1].x, k1.x, s1))));
                    s2 = fmaf(q[d+2].w, k2.w, fmaf(q[d+2].z, k2.z, fmaf(q[d+2].y, k2.y, fmaf(q[d+2].x, k2.x, s2))));
                    s3 = fmaf(q[d+3].w, k3.w, fmaf(q[d+3].z, k3.z, fmaf(q[d+3].y, k3.y, fmaf(q[d+3].x, k3.x, s3))));
                }
                sv[j] = (s0 + s1) + (s2 + s3);
            }
            float mt = sv[0];
            #pragma unroll
            for (int j = 1; j < 16; j++) mt = fmaxf(mt, sv[j]);
            float nm = fmaxf(m, mt);
            float alpha = __expf(m - nm);
            m = nm;
            l *= alpha;
            #pragma unroll
            for (int i = 0; i < 16; i++) {
                o[i].x *= alpha; o[i].y *= alpha; o[i].z *= alpha; o[i].w *= alpha;
            }
            #pragma unroll
            for (int j = 0; j < 16; j++) {
                float p = __expf(sv[j] - nm);
                l += p;
                const float4* vr = (const float4*)&Vs[jc + j][0];
                #pragma unroll
                for (int d = 0; d < 16; d++) {
                    float4 vv = vr[d];
                    o[d].x = fmaf(p, vv.x, o[d].x);
                    o[d].y = fmaf(p, vv.y, o[d].y);
                    o[d].z = fmaf(p, vv.z, o[d].z);
                    o[d].w = fmaf(p, vv.w, o[d].w);
                }
            }
        }
    }

    float inv = __fdividef(1.f, l);
    float* op = O + headoff + (size_t)qrow * HIDDEN;
    #pragma unroll
    for (int i = 0; i < 16; i++) {
        float4 t = make_float4(o[i].x * inv, o[i].y * inv, o[i].z * inv, o[i].w * inv);
        ((float4*)op)[i] = t;
    }
}

// ---------------------------------------------------------------------------
// Launch
// ---------------------------------------------------------------------------
extern "C" void kernel_launch(void* const* d_in, const int* in_sizes, int n_in,
                              void* d_out, int out_size)
{
    const float* x   = (const float*)d_in[0];
    const float* Wq  = (const float*)d_in[1];
    const float* bq  = (const float*)d_in[2];
    const float* Wk  = (const float*)d_in[3];
    const float* bk  = (const float*)d_in[4];
    const float* Wv  = (const float*)d_in[5];
    const float* bv  = (const float*)d_in[6];
    const float* Wo  = (const float*)d_in[7];
    const float* bo  = (const float*)d_in[8];
    const float* lng = (const float*)d_in[9];
    const float* lnb = (const float*)d_in[10];
    float* out = (float*)d_out;

    float *xn, *q, *k, *v, *ctx;
    cudaGetSymbolAddress((void**)&xn,  g_xn);
    cudaGetSymbolAddress((void**)&q,   g_q);
    cudaGetSymbolAddress((void**)&k,   g_k);
    cudaGetSymbolAddress((void**)&v,   g_v);
    cudaGetSymbolAddress((void**)&ctx, g_ctx);

    ln_kernel<<<M_TOT, 256>>>(x, lng, lnb, xn);

    dim3 ggrid(HIDDEN / GBN, M_TOT / GBM);     // (8, 32)
    gemm_kernel<<<ggrid, 256>>>(xn, Wq, bq, nullptr, q,   M_TOT, HIDDEN, HIDDEN);
    gemm_kernel<<<ggrid, 256>>>(xn, Wk, bk, nullptr, k,   M_TOT, HIDDEN, HIDDEN);
    gemm_kernel<<<ggrid, 256>>>(xn, Wv, bv, nullptr, v,   M_TOT, HIDDEN, HIDDEN);

    attn_kernel<<<dim3(SEQ / 128, HEADS, BATCH), 128>>>(q, k, v, ctx);

    gemm_kernel<<<ggrid, 256>>>(ctx, Wo, bo, x, out, M_TOT, HIDDEN, HIDDEN);
}

// round 6
// speedup vs baseline: 1.2409x; 1.2409x over previous
#include <cuda_runtime.h>
#include <cuda_bf16.h>
#include <cstdint>

#define HIDDEN 1024
#define HEADS  16
#define HEADD  64
#define BATCH  2
#define SEQ    2048
#define M_TOT  (BATCH * SEQ)   // 4096 rows

// ---------------------------------------------------------------------------
// Scratch (no cudaMalloc allowed)
// ---------------------------------------------------------------------------
__device__ float g_xn [M_TOT * HIDDEN];
__device__ float g_q  [M_TOT * HIDDEN];
__device__ float g_k  [M_TOT * HIDDEN];
__device__ float g_v  [M_TOT * HIDDEN];
__device__ float g_ctx[M_TOT * HIDDEN];

// ---------------------------------------------------------------------------
// Base-ISA tensor-core helpers (sm_80+ : valid under compute_103)
// ---------------------------------------------------------------------------
__device__ __forceinline__ uint32_t smem_u32(const void* p) {
    uint32_t a;
    asm("{ .reg .u64 t; cvta.to.shared.u64 t, %1; cvt.u32.u64 %0, t; }"
        : "=r"(a) : "l"(p));
    return a;
}

__device__ __forceinline__ void ldsm_x4(uint32_t* r, uint32_t addr) {
    asm volatile("ldmatrix.sync.aligned.m8n8.x4.shared.b16 {%0,%1,%2,%3}, [%4];"
        : "=r"(r[0]), "=r"(r[1]), "=r"(r[2]), "=r"(r[3]) : "r"(addr));
}

__device__ __forceinline__ void mma_bf16(float* c, const uint32_t* a, const uint32_t* b) {
    asm volatile(
        "mma.sync.aligned.m16n8k16.row.col.f32.bf16.bf16.f32 "
        "{%0,%1,%2,%3}, {%4,%5,%6,%7}, {%8,%9}, {%0,%1,%2,%3};"
        : "+f"(c[0]), "+f"(c[1]), "+f"(c[2]), "+f"(c[3])
        : "r"(a[0]), "r"(a[1]), "r"(a[2]), "r"(a[3]), "r"(b[0]), "r"(b[1]));
}

// ---------------------------------------------------------------------------
// LayerNorm: one block per row, 256 threads, float4 loads
// ---------------------------------------------------------------------------
__global__ __launch_bounds__(256) void ln_kernel(
    const float* __restrict__ x, const float* __restrict__ gam,
    const float* __restrict__ bet, float* __restrict__ out)
{
    int row = blockIdx.x;
    int tid = threadIdx.x;
    const float4* xr = (const float4*)(x + (size_t)row * HIDDEN);
    float4 v = xr[tid];
    float s  = v.x + v.y + v.z + v.w;
    float ss = v.x * v.x + v.y * v.y + v.z * v.z + v.w * v.w;
    #pragma unroll
    for (int o = 16; o > 0; o >>= 1) {
        s  += __shfl_xor_sync(0xFFFFFFFFu, s,  o);
        ss += __shfl_xor_sync(0xFFFFFFFFu, ss, o);
    }
    __shared__ float sh_s[8], sh_ss[8];
    int w = tid >> 5, lane = tid & 31;
    if (lane == 0) { sh_s[w] = s; sh_ss[w] = ss; }
    __syncthreads();
    s = 0.f; ss = 0.f;
    #pragma unroll
    for (int i = 0; i < 8; i++) { s += sh_s[i]; ss += sh_ss[i]; }
    float mean = s * (1.f / HIDDEN);
    float var  = ss * (1.f / HIDDEN) - mean * mean;
    float rstd = rsqrtf(var + 1e-5f);
    float4 g = ((const float4*)gam)[tid];
    float4 b = ((const float4*)bet)[tid];
    float4 o;
    o.x = (v.x - mean) * rstd * g.x + b.x;
    o.y = (v.y - mean) * rstd * g.y + b.y;
    o.z = (v.z - mean) * rstd * g.z + b.z;
    o.w = (v.w - mean) * rstd * g.w + b.w;
    ((float4*)(out + (size_t)row * HIDDEN))[tid] = o;
}

// ---------------------------------------------------------------------------
// mma.sync split-bf16 GEMM: C[M,N] = A[M,K] * W[N,K]^T + bias (+ residual)
// CTA 128x128, 8 warps (2x4), warp tile 64x32, K chunk 32, double buffer.
// fp32 = hi(bf16 trunc) + lo(bf16 rn):  C = Ah*Wh + Ah*Wl + Al*Wh
// smem tile layout: 128 rows x 32 bf16, row stride 80B (conflict-free ldmatrix)
// ---------------------------------------------------------------------------
#define KCH      32
#define NCHUNK   (HIDDEN / KCH)       // 32
#define TSTRIDE  80                   // bytes per 32-bf16 row (padded)
#define TILE_B   (128 * TSTRIDE)      // 10240
#define STAGE_B  (4 * TILE_B)         // Ah, Al, Wh, Wl = 40960
#define GEMM_SMEM (2 * STAGE_B)       // 81920

__global__ __launch_bounds__(256) void gemm_mma(
    const float* __restrict__ A, const float* __restrict__ W,
    const float* __restrict__ bias, const float* __restrict__ resid,
    float* __restrict__ C)
{
    extern __shared__ char smem[];
    uint32_t sb = smem_u32(smem);
    int tid  = threadIdx.x;
    int lane = tid & 31;
    int wid  = tid >> 5;
    int wm   = wid & 1;          // 0..1 : 64-row block
    int wn   = wid >> 1;         // 0..3 : 32-col block
    int bn = blockIdx.x, bm = blockIdx.y;

    // ---- loader mapping: 2 threads per row, 16 floats each
    int lrow = tid >> 1;         // 0..127
    int lhalf = tid & 1;         // k-offset 0 / 16
    const float* Ap = A + (size_t)(bm * 128 + lrow) * HIDDEN + lhalf * 16;
    const float* Wp = W + (size_t)(bn * 128 + lrow) * HIDDEN + lhalf * 16;
    uint32_t st_off = (uint32_t)(lrow * TSTRIDE + lhalf * 32);

    float acc[4][4][4];
    #pragma unroll
    for (int i = 0; i < 4; i++)
        #pragma unroll
        for (int j = 0; j < 4; j++)
            #pragma unroll
            for (int r = 0; r < 4; r++) acc[i][j][r] = 0.f;

    // ldmatrix per-lane addressing (same formula for A and B tiles)
    uint32_t lr16 = (uint32_t)(lane & 15);
    uint32_t lc16 = (uint32_t)((lane >> 4) * 16);
    uint32_t a_row = (uint32_t)(wm * 64) + lr16;   // + mi*16
    uint32_t b_row = (uint32_t)(wn * 32) + lr16;   // + g*16

    float4 va[4], vw[4];
    #pragma unroll
    for (int j = 0; j < 4; j++) {
        va[j] = *(const float4*)(Ap + j * 4);
        vw[j] = *(const float4*)(Wp + j * 4);
    }

    for (int c = 0; c < NCHUNK; ++c) {
        int s = c & 1;
        char* stg = smem + s * STAGE_B;
        uint32_t stg_u = sb + s * STAGE_B;

        __syncthreads();
        // ---- split-convert + store (A -> tiles 0/1, W -> tiles 2/3)
        {
            uint32_t h[8], l[8];
            #pragma unroll
            for (int j = 0; j < 4; j++) {
                float4 v = va[j];
                uint32_t bx = __float_as_uint(v.x), by = __float_as_uint(v.y);
                uint32_t bz = __float_as_uint(v.z), bw = __float_as_uint(v.w);
                h[2*j]   = __byte_perm(bx, by, 0x7632);
                h[2*j+1] = __byte_perm(bz, bw, 0x7632);
                float lx = v.x - __uint_as_float(bx & 0xFFFF0000u);
                float ly = v.y - __uint_as_float(by & 0xFFFF0000u);
                float lz = v.z - __uint_as_float(bz & 0xFFFF0000u);
                float lw = v.w - __uint_as_float(bw & 0xFFFF0000u);
                __nv_bfloat162 p0 = __floats2bfloat162_rn(lx, ly);
                __nv_bfloat162 p1 = __floats2bfloat162_rn(lz, lw);
                l[2*j]   = *(uint32_t*)&p0;
                l[2*j+1] = *(uint32_t*)&p1;
            }
            *(uint4*)(stg + st_off)               = make_uint4(h[0], h[1], h[2], h[3]);
            *(uint4*)(stg + st_off + 16)          = make_uint4(h[4], h[5], h[6], h[7]);
            *(uint4*)(stg + TILE_B + st_off)      = make_uint4(l[0], l[1], l[2], l[3]);
            *(uint4*)(stg + TILE_B + st_off + 16) = make_uint4(l[4], l[5], l[6], l[7]);
            #pragma unroll
            for (int j = 0; j < 4; j++) {
                float4 v = vw[j];
                uint32_t bx = __float_as_uint(v.x), by = __float_as_uint(v.y);
                uint32_t bz = __float_as_uint(v.z), bw = __float_as_uint(v.w);
                h[2*j]   = __byte_perm(bx, by, 0x7632);
                h[2*j+1] = __byte_perm(bz, bw, 0x7632);
                float lx = v.x - __uint_as_float(bx & 0xFFFF0000u);
                float ly = v.y - __uint_as_float(by & 0xFFFF0000u);
                float lz = v.z - __uint_as_float(bz & 0xFFFF0000u);
                float lw = v.w - __uint_as_float(bw & 0xFFFF0000u);
                __nv_bfloat162 p0 = __floats2bfloat162_rn(lx, ly);
                __nv_bfloat162 p1 = __floats2bfloat162_rn(lz, lw);
                l[2*j]   = *(uint32_t*)&p0;
                l[2*j+1] = *(uint32_t*)&p1;
            }
            *(uint4*)(stg + 2*TILE_B + st_off)      = make_uint4(h[0], h[1], h[2], h[3]);
            *(uint4*)(stg + 2*TILE_B + st_off + 16) = make_uint4(h[4], h[5], h[6], h[7]);
            *(uint4*)(stg + 3*TILE_B + st_off)      = make_uint4(l[0], l[1], l[2], l[3]);
            *(uint4*)(stg + 3*TILE_B + st_off + 16) = make_uint4(l[4], l[5], l[6], l[7]);
        }
        __syncthreads();

        // ---- prefetch next chunk (LDG latency overlaps MMA below)
        if (c + 1 < NCHUNK) {
            int k0 = (c + 1) * KCH;
            #pragma unroll
            for (int j = 0; j < 4; j++) {
                va[j] = *(const float4*)(Ap + k0 + j * 4);
                vw[j] = *(const float4*)(Wp + k0 + j * 4);
            }
        }

        // ---- MMA phase: 2 ksteps of 16
        uint32_t aHi = stg_u +              a_row * TSTRIDE + lc16;
        uint32_t aLo = stg_u + TILE_B     + a_row * TSTRIDE + lc16;
        uint32_t bHi = stg_u + 2 * TILE_B + b_row * TSTRIDE + lc16;
        uint32_t bLo = stg_u + 3 * TILE_B + b_row * TSTRIDE + lc16;
        #pragma unroll
        for (int ks = 0; ks < 2; ks++) {
            uint32_t koff = (uint32_t)(ks * 32);   // 16 bf16 = 32B
            uint32_t ah[4][4], al[4][4], bh[4][2], bl[4][2];
            #pragma unroll
            for (int mi = 0; mi < 4; mi++) {
                ldsm_x4(ah[mi], aHi + mi * (16 * TSTRIDE) + koff);
                ldsm_x4(al[mi], aLo + mi * (16 * TSTRIDE) + koff);
            }
            #pragma unroll
            for (int g = 0; g < 2; g++) {
                uint32_t t[4];
                ldsm_x4(t, bHi + g * (16 * TSTRIDE) + koff);
                bh[2*g][0] = t[0]; bh[2*g][1] = t[2];
                bh[2*g+1][0] = t[1]; bh[2*g+1][1] = t[3];
                ldsm_x4(t, bLo + g * (16 * TSTRIDE) + koff);
                bl[2*g][0] = t[0]; bl[2*g][1] = t[2];
                bl[2*g+1][0] = t[1]; bl[2*g+1][1] = t[3];
            }
            #pragma unroll
            for (int mi = 0; mi < 4; mi++)
                #pragma unroll
                for (int nj = 0; nj < 4; nj++) {
                    mma_bf16(acc[mi][nj], ah[mi], bh[nj]);
                    mma_bf16(acc[mi][nj], ah[mi], bl[nj]);
                    mma_bf16(acc[mi][nj], al[mi], bh[nj]);
                }
        }
    }

    // ---- epilogue: fragment -> global, fused bias (+ residual)
    int r0    = bm * 128 + wm * 64 + (lane >> 2);
    int cbase = bn * 128 + wn * 32 + (lane & 3) * 2;
    #pragma unroll
    for (int nj = 0; nj < 4; nj++) {
        int gc = cbase + nj * 8;
        float2 bv = *(const float2*)(bias + gc);
        #pragma unroll
        for (int mi = 0; mi < 4; mi++) {
            int gr = r0 + mi * 16;
            float2 o0, o1;
            o0.x = acc[mi][nj][0] + bv.x;  o0.y = acc[mi][nj][1] + bv.y;
            o1.x = acc[mi][nj][2] + bv.x;  o1.y = acc[mi][nj][3] + bv.y;
            if (resid) {
                float2 ra = *(const float2*)(resid + (size_t)gr * HIDDEN + gc);
                float2 rb = *(const float2*)(resid + (size_t)(gr + 8) * HIDDEN + gc);
                o0.x += ra.x; o0.y += ra.y;
                o1.x += rb.x; o1.y += rb.y;
            }
            *(float2*)(C + (size_t)gr * HIDDEN + gc)       = o0;
            *(float2*)(C + (size_t)(gr + 8) * HIDDEN + gc) = o1;
        }
    }
}

// ---------------------------------------------------------------------------
// Flash attention (fp32): 1 thread = 1 query row, K/V staged in 64-row tiles
// ---------------------------------------------------------------------------
__global__ __launch_bounds__(128) void attn_kernel(
    const float* __restrict__ Q, const float* __restrict__ Kp,
    const float* __restrict__ V, float* __restrict__ O)
{
    __shared__ float Ks[64][64];
    __shared__ float Vs[64][64];
    int tid  = threadIdx.x;
    int h = blockIdx.y, b = blockIdx.z;
    int qrow = blockIdx.x * 128 + tid;
    size_t headoff = (size_t)b * SEQ * HIDDEN + (size_t)h * HEADD;

    const float4* qp = (const float4*)(Q + headoff + (size_t)qrow * HIDDEN);
    float4 q[16];
    #pragma unroll
    for (int i = 0; i < 16; i++) {
        float4 t = qp[i];
        q[i] = make_float4(t.x * 0.125f, t.y * 0.125f, t.z * 0.125f, t.w * 0.125f);
    }
    float4 o[16];
    #pragma unroll
    for (int i = 0; i < 16; i++) o[i] = make_float4(0.f, 0.f, 0.f, 0.f);
    float m = -1e30f, l = 0.f;

    for (int kt = 0; kt < SEQ; kt += 64) {
        const float4* kp = (const float4*)(Kp + headoff + (size_t)kt * HIDDEN);
        const float4* vp = (const float4*)(V  + headoff + (size_t)kt * HIDDEN);
        __syncthreads();
        #pragma unroll
        for (int i = 0; i < 8; i++) {
            int idx = tid + i * 128;
            int r = idx >> 4, c = idx & 15;
            ((float4*)Ks)[idx] = kp[(size_t)r * (HIDDEN / 4) + c];
            ((float4*)Vs)[idx] = vp[(size_t)r * (HIDDEN / 4) + c];
        }
        __syncthreads();

        for (int jc = 0; jc < 64; jc += 16) {
            float sv[16];
            #pragma unroll
            for (int j = 0; j < 16; j++) {
                const float4* kr = (const float4*)&Ks[jc + j][0];
                float s0 = 0.f, s1 = 0.f, s2 = 0.f, s3 = 0.f;
                #pragma unroll
                for (int d = 0; d < 16; d += 4) {
                    float4 k0 = kr[d], k1 = kr[d + 1], k2 = kr[d + 2], k3 = kr[d + 3];
                    s0 = fmaf(q[d].w,   k0.w, fmaf(q[d].z,   k0.z, fmaf(q[d].y,   k0.y, fmaf(q[d].x,   k0.x, s0))));
                    s1 = fmaf(q[d+1].w, k1.w, fmaf(q[d+1].z, k1.z, fmaf(q[d+1].y, k1.y, fmaf(q[d+1].x, k1.x, s1))));
                    s2 = fmaf(q[d+2].w, k2.w, fmaf(q[d+2].z, k2.z, fmaf(q[d+2].y, k2.y, fmaf(q[d+2].x, k2.x, s2))));
                    s3 = fmaf(q[d+3].w, k3.w, fmaf(q[d+3].z, k3.z, fmaf(q[d+3].y, k3.y, fmaf(q[d+3].x, k3.x, s3))));
                }
                sv[j] = (s0 + s1) + (s2 + s3);
            }
            float mt = sv[0];
            #pragma unroll
            for (int j = 1; j < 16; j++) mt = fmaxf(mt, sv[j]);
            float nm = fmaxf(m, mt);
            float alpha = __expf(m - nm);
            m = nm;
            l *= alpha;
            #pragma unroll
            for (int i = 0; i < 16; i++) {
                o[i].x *= alpha; o[i].y *= alpha; o[i].z *= alpha; o[i].w *= alpha;
            }
            #pragma unroll
            for (int j = 0; j < 16; j++) {
                float p = __expf(sv[j] - nm);
                l += p;
                const float4* vr = (const float4*)&Vs[jc + j][0];
                #pragma unroll
                for (int d = 0; d < 16; d++) {
                    float4 vv = vr[d];
                    o[d].x = fmaf(p, vv.x, o[d].x);
                    o[d].y = fmaf(p, vv.y, o[d].y);
                    o[d].z = fmaf(p, vv.z, o[d].z);
                    o[d].w = fmaf(p, vv.w, o[d].w);
                }
            }
        }
    }

    float inv = __fdividef(1.f, l);
    float* op = O + headoff + (size_t)qrow * HIDDEN;
    #pragma unroll
    for (int i = 0; i < 16; i++) {
        float4 t = make_float4(o[i].x * inv, o[i].y * inv, o[i].z * inv, o[i].w * inv);
        ((float4*)op)[i] = t;
    }
}

// ---------------------------------------------------------------------------
// Launch
// ---------------------------------------------------------------------------
extern "C" void kernel_launch(void* const* d_in, const int* in_sizes, int n_in,
                              void* d_out, int out_size)
{
    const float* x   = (const float*)d_in[0];
    const float* Wq  = (const float*)d_in[1];
    const float* bq  = (const float*)d_in[2];
    const float* Wk  = (const float*)d_in[3];
    const float* bk  = (const float*)d_in[4];
    const float* Wv  = (const float*)d_in[5];
    const float* bv  = (const float*)d_in[6];
    const float* Wo  = (const float*)d_in[7];
    const float* bo  = (const float*)d_in[8];
    const float* lng = (const float*)d_in[9];
    const float* lnb = (const float*)d_in[10];
    float* out = (float*)d_out;

    float *xn, *q, *k, *v, *ctx;
    cudaGetSymbolAddress((void**)&xn,  g_xn);
    cudaGetSymbolAddress((void**)&q,   g_q);
    cudaGetSymbolAddress((void**)&k,   g_k);
    cudaGetSymbolAddress((void**)&v,   g_v);
    cudaGetSymbolAddress((void**)&ctx, g_ctx);

    cudaFuncSetAttribute(gemm_mma, cudaFuncAttributeMaxDynamicSharedMemorySize, GEMM_SMEM);

    ln_kernel<<<M_TOT, 256>>>(x, lng, lnb, xn);

    dim3 ggrid(HIDDEN / 128, M_TOT / 128);     // (8, 32)
    gemm_mma<<<ggrid, 256, GEMM_SMEM>>>(xn, Wq, bq, nullptr, q);
    gemm_mma<<<ggrid, 256, GEMM_SMEM>>>(xn, Wk, bk, nullptr, k);
    gemm_mma<<<ggrid, 256, GEMM_SMEM>>>(xn, Wv, bv, nullptr, v);

    attn_kernel<<<dim3(SEQ / 128, HEADS, BATCH), 128>>>(q, k, v, ctx);

    gemm_mma<<<ggrid, 256, GEMM_SMEM>>>(ctx, Wo, bo, x, out);
}